// round 10
// baseline (speedup 1.0000x reference)
#include <cuda_runtime.h>
#include <cstdint>

#define MAX_NODES 100000
#define NB 148      // one CTA per SM -> single wave, co-residency guaranteed
#define TB 1024

// Single contiguous scratch block -> one captured cudaMemsetAsync clears all
// (accumulators + partials + finalize ticket + grid-barrier words).
struct Scratch {
    float4   acc[MAX_NODES];  // (c4, s4, deg, pad)
    float    part[2];         // [0] pair_loss_sum, [1] n_pairs
    unsigned done;            // finalize ticket
    unsigned bar;             // grid-barrier arrival counter
    unsigned flag;            // grid-barrier release flag
};
__device__ Scratch g_s;

__device__ __forceinline__ void red_v4(float4* addr, float a, float b, float c, float d) {
    asm volatile("red.global.add.v4.f32 [%0], {%1, %2, %3, %4};"
                 :: "l"(addr), "f"(a), "f"(b), "f"(c), "f"(d)
                 : "memory");
}

__global__ __launch_bounds__(TB, 1)
void fused_kernel(const float* __restrict__ pos,
                  const int*   __restrict__ ei,
                  int E, int N, float* __restrict__ out) {
    const int tid    = blockIdx.x * blockDim.x + threadIdx.x;
    const int stride = NB * TB;

    // ---- Phase 1: edge scatter (grid-stride) ----
    const float2* p2 = (const float2*)pos;
    for (int e = tid; e < E; e += stride) {
        int s = ei[e];
        int t = ei[E + e];
        float2 ps = __ldg(p2 + s);
        float2 pt = __ldg(p2 + t);
        float dx = pt.x - ps.x;
        float dy = pt.y - ps.y;
        float nrm = sqrtf(fmaf(dx, dx, dy * dy));
        float inv = 1.0f / fmaxf(nrm, 1e-8f);
        float u = dx * inv, v = dy * inv;
        // cos(2t) = u^2 - v^2 ; sin(2t) = 2uv ; double-angle again for 4t.
        float a = u * u - v * v;
        float b = 2.0f * u * v;
        float c4 = a * a - b * b;
        float s4 = 2.0f * a * b;
        // 4-theta invariant under d -> -d: identical payload to both endpoints.
        red_v4(&g_s.acc[s], c4, s4, 1.0f, 0.0f);
        red_v4(&g_s.acc[t], c4, s4, 1.0f, 0.0f);
    }

    // ---- Grid barrier (all NB blocks are resident: single wave) ----
    __syncthreads();
    if (threadIdx.x == 0) {
        __threadfence();                       // publish our REDs
        unsigned t = atomicAdd(&g_s.bar, 1u) + 1u;
        if (t == NB) {
            atomicExch(&g_s.flag, 1u);         // release
        } else {
            volatile unsigned* f = &g_s.flag;
            while (*f == 0u) __nanosleep(32);
        }
        __threadfence();                       // acquire
    }
    __syncthreads();

    // ---- Phase 2: node reduction ----
    float pl = 0.0f, np = 0.0f;
    for (int i = tid; i < N; i += stride) {
        float4 acc = g_s.acc[i];
        float k = acc.z;
        // sum_{i<j}(dot^2 - dot^4) = (k^2 - C4^2 - S4^2)/16 (incl. 0.5 pair factor)
        pl += (k * k - (acc.x * acc.x + acc.y * acc.y)) * 0.0625f;
        np += 0.5f * k * (k - 1.0f);
    }

    #pragma unroll
    for (int o = 16; o > 0; o >>= 1) {
        pl += __shfl_down_sync(0xffffffffu, pl, o);
        np += __shfl_down_sync(0xffffffffu, np, o);
    }
    __shared__ float s_pl[32];
    __shared__ float s_np[32];
    int lane = threadIdx.x & 31;
    int wid  = threadIdx.x >> 5;
    if (lane == 0) { s_pl[wid] = pl; s_np[wid] = np; }
    __syncthreads();
    if (wid == 0) {
        int nw = TB / 32;
        pl = (lane < nw) ? s_pl[lane] : 0.0f;
        np = (lane < nw) ? s_np[lane] : 0.0f;
        #pragma unroll
        for (int o = 16; o > 0; o >>= 1) {
            pl += __shfl_down_sync(0xffffffffu, pl, o);
            np += __shfl_down_sync(0xffffffffu, np, o);
        }
        if (lane == 0) {
            atomicAdd(&g_s.part[0], pl);
            atomicAdd(&g_s.part[1], np);
            __threadfence();
            unsigned done = atomicAdd(&g_s.done, 1u);
            if (done == NB - 1) {
                float a = atomicAdd(&g_s.part[0], 0.0f);
                float b = atomicAdd(&g_s.part[1], 0.0f);
                out[0] = a / fmaxf(b, 1.0f);
            }
        }
    }
}

extern "C" void kernel_launch(void* const* d_in, const int* in_sizes, int n_in,
                              void* d_out, int out_size) {
    const float* pos = (const float*)d_in[0];
    const int*   ei  = (const int*)d_in[2];
    int N = in_sizes[0] / 2;      // node_positions: (1, N, 2)
    int E = in_sizes[2] / 2;      // edge_index: (2, E)

    static bool configured = false;
    if (!configured) {
        cudaFuncSetAttribute(fused_kernel,
                             cudaFuncAttributePreferredSharedMemoryCarveout, 0);
        configured = true;
    }

    void* scratch_ptr = nullptr;
    cudaGetSymbolAddress(&scratch_ptr, g_s);
    cudaMemsetAsync(scratch_ptr, 0, sizeof(Scratch));  // captured memset node

    fused_kernel<<<NB, TB>>>(pos, ei, E, N, (float*)d_out);
}

// round 11
// speedup vs baseline: 1.1129x; 1.1129x over previous
#include <cuda_runtime.h>
#include <cstdint>

#define MAX_NODES 100000
#define NODE_TB   1024
#define NODE_GRID 148   // 148*1024 = 151552 >= 100000, single wave, 1 node/thread

// Single contiguous scratch block -> one captured cudaMemsetAsync clears all.
struct Scratch {
    float4   acc[MAX_NODES];  // (c4, s4, deg, pad)
    float    part[2];         // [0] pair_loss_sum, [1] n_pairs
    unsigned done;
};
__device__ Scratch g_s;

__device__ __forceinline__ void red_v4(float4* addr, float a, float b, float c, float d) {
    asm volatile("red.global.add.v4.f32 [%0], {%1, %2, %3, %4};"
                 :: "l"(addr), "f"(a), "f"(b), "f"(c), "f"(d)
                 : "memory");
}

__global__ void edge_kernel(const float* __restrict__ pos,
                            const int*   __restrict__ ei,
                            int E) {
    int e = blockIdx.x * blockDim.x + threadIdx.x;
    if (e >= E) return;
    int s = ei[e];
    int t = ei[E + e];
    float2 ps = __ldg((const float2*)pos + s);
    float2 pt = __ldg((const float2*)pos + t);
    float dx = pt.x - ps.x;
    float dy = pt.y - ps.y;
    float nrm = sqrtf(fmaf(dx, dx, dy * dy));
    float inv = 1.0f / fmaxf(nrm, 1e-8f);
    float u = dx * inv, v = dy * inv;
    // cos(2t) = u^2 - v^2 ; sin(2t) = 2uv ; double-angle again for 4t.
    float a = u * u - v * v;
    float b = 2.0f * u * v;
    float c4 = a * a - b * b;
    float s4 = 2.0f * a * b;
    // 4-theta terms are invariant under d -> -d: identical payload to both endpoints.
    red_v4(&g_s.acc[s], c4, s4, 1.0f, 0.0f);
    red_v4(&g_s.acc[t], c4, s4, 1.0f, 0.0f);
}

__global__ __launch_bounds__(NODE_TB, 1)
void node_kernel(int n, float* __restrict__ out) {
    const int i = blockIdx.x * blockDim.x + threadIdx.x;

    float pl = 0.0f, np = 0.0f;
    if (i < n) {
        float4 acc = g_s.acc[i];
        float k = acc.z;
        // sum_{i<j}(dot^2 - dot^4) = (k^2 - C4^2 - S4^2)/16 (incl. 0.5 pair factor)
        pl = (k * k - (acc.x * acc.x + acc.y * acc.y)) * 0.0625f;
        np = 0.5f * k * (k - 1.0f);
    }

    #pragma unroll
    for (int o = 16; o > 0; o >>= 1) {
        pl += __shfl_down_sync(0xffffffffu, pl, o);
        np += __shfl_down_sync(0xffffffffu, np, o);
    }
    __shared__ float s_pl[32];
    __shared__ float s_np[32];
    int lane = threadIdx.x & 31;
    int wid  = threadIdx.x >> 5;
    if (lane == 0) { s_pl[wid] = pl; s_np[wid] = np; }
    __syncthreads();
    if (wid == 0) {
        pl = s_pl[lane];
        np = s_np[lane];
        #pragma unroll
        for (int o = 16; o > 0; o >>= 1) {
            pl += __shfl_down_sync(0xffffffffu, pl, o);
            np += __shfl_down_sync(0xffffffffu, np, o);
        }
        if (lane == 0) {
            atomicAdd(&g_s.part[0], pl);
            atomicAdd(&g_s.part[1], np);
            __threadfence();
            unsigned done = atomicAdd(&g_s.done, 1u);
            if (done == gridDim.x - 1) {
                // All prior atomics are globally visible (fence + ticket order);
                // volatile loads avoid two extra ATOMG round trips in the tail.
                volatile float* p = g_s.part;
                float a = p[0];
                float b = p[1];
                out[0] = a / fmaxf(b, 1.0f);
            }
        }
    }
}

extern "C" void kernel_launch(void* const* d_in, const int* in_sizes, int n_in,
                              void* d_out, int out_size) {
    const float* pos = (const float*)d_in[0];
    const int*   ei  = (const int*)d_in[2];
    int N = in_sizes[0] / 2;      // node_positions: (1, N, 2)
    int E = in_sizes[2] / 2;      // edge_index: (2, E)

    static bool configured = false;
    if (!configured) {
        cudaFuncSetAttribute(edge_kernel,
                             cudaFuncAttributePreferredSharedMemoryCarveout, 0);
        configured = true;
    }

    void* scratch_ptr = nullptr;
    cudaGetSymbolAddress(&scratch_ptr, g_s);
    cudaMemsetAsync(scratch_ptr, 0, sizeof(Scratch));  // captured memset node

    const int TB = 256;
    edge_kernel<<<(E + TB - 1) / TB, TB>>>(pos, ei, E);
    node_kernel<<<NODE_GRID, NODE_TB>>>(N, (float*)d_out);
}